// round 1
// baseline (speedup 1.0000x reference)
#include <cuda_runtime.h>

// Problem constants: x shape (N=2, D=192, H=256, W=512), float32.
#define DIMD 192
#define HWD  131072          // H*W = 256*512
#define BLK  128             // threads per block = pixels per block
#define NPIX 262144          // N*H*W
#define SMEM_BYTES (DIMD * BLK * 4)   // 98304 B

// Exact-order 5-tap blur at depth d for this thread's column, with the
// interval [ZA,ZB] zeroed AFTER blurring (x_blur * ~mask semantics).
// Reproduces the reference's add order ((((x[d-2]+x[d-1])+x[d])+x[d+1])+x[d+2])/5
// with zero padding, using IEEE round-to-nearest division (immune to fast-math).
__device__ __forceinline__ float blur5(const float* __restrict__ col, int d,
                                       int ZA, int ZB)
{
    if (d >= ZA && d <= ZB) return 0.0f;
    float a = (d >= 2)        ? col[(d - 2) * BLK] : 0.0f;
    a = a + ((d >= 1)         ? col[(d - 1) * BLK] : 0.0f);
    a = a +                     col[d * BLK];
    a = a + ((d + 1 < DIMD)   ? col[(d + 1) * BLK] : 0.0f);
    a = a + ((d + 2 < DIMD)   ? col[(d + 2) * BLK] : 0.0f);
    return __fdiv_rn(a, 5.0f);
}

// _modal_mask collapsed to an interval [lo,hi].
//  - argmax (first occurrence) over blurred column with [ZA,ZB] zeroed
//  - index_r: (first i > idx with b[i]-b[i-1] > 0) - 1; i==D sentinel 1-b>0 always fires
//  - index_l: last i <= idx with b[i]-b[i-1] < 0; i==0 sentinel b[0]-1<0 always fires
//  - valid = |2*idx - ir - il| < 3 ? [il,ir] : [idx-r, idx+r], r=min(ir-idx, idx-il)
__device__ __forceinline__ void modal_interval(const float* __restrict__ col,
                                               int ZA, int ZB,
                                               int& lo, int& hi)
{
    // ---- argmax pass with rolling window (1 smem read / step) ----
    float best = -1.0f;
    int   idx  = 0;
    float xm2 = 0.0f, xm1 = 0.0f, x0 = col[0], x1 = col[BLK];
    #pragma unroll 4
    for (int d = 0; d < DIMD; ++d) {
        float x2 = (d + 2 < DIMD) ? col[(d + 2) * BLK] : 0.0f;
        float b  = __fdiv_rn((((xm2 + xm1) + x0) + x1) + x2, 5.0f);
        if (d >= ZA && d <= ZB) b = 0.0f;
        if (b > best) { best = b; idx = d; }   // strict > == first-occurrence argmax
        xm2 = xm1; xm1 = x0; x0 = x1; x1 = x2;
    }

    // ---- right scan: first strictly-increasing step after idx ----
    int i = idx + 1;
    float bprev = best;                         // b at idx (post-zeroing)
    while (i < DIMD) {
        float bi = blur5(col, i, ZA, ZB);
        if (bi > bprev) break;                  // diff[i] > 0
        bprev = bi; ++i;
    }
    const int ir = i - 1;                       // i==DIMD: sentinel diff=1-b>0 -> ir=D-1

    // ---- left scan: last strictly-decreasing step at or below idx ----
    i = idx;
    float bcur = best;
    while (i >= 1) {
        float bm = blur5(col, i - 1, ZA, ZB);
        if (bcur < bm) break;                   // diff[i] = b[i]-b[i-1] < 0
        bcur = bm; --i;
    }
    const int il = i;                           // i==0: sentinel b[0]-1<0

    int dev = 2 * idx - ir - il;
    dev = (dev < 0) ? -dev : dev;
    if (dev < 3) { lo = il; hi = ir; }
    else {
        int rr = min(ir - idx, idx - il);
        lo = idx - rr; hi = idx + rr;
    }
}

__global__ void __launch_bounds__(BLK, 2)
dme_kernel(const float* __restrict__ x, float* __restrict__ out)
{
    extern __shared__ float s[];                // [DIMD][BLK]
    const int tid  = threadIdx.x;
    const int pix0 = blockIdx.x * BLK;          // blocks never straddle n (HWD % BLK == 0)
    const int n    = pix0 / HWD;
    const int hw   = pix0 % HWD;
    const float* __restrict__ xg = x + (size_t)n * DIMD * HWD + hw;

    // Coalesced stage-in: each iteration reads one 512B d-slice segment.
    #pragma unroll 8
    for (int d = 0; d < DIMD; ++d)
        s[d * BLK + tid] = xg[(size_t)d * HWD + tid];
    __syncthreads();

    const float* col = s + tid;                 // lane-private bank column

    int lo1, hi1, lo2, hi2;
    modal_interval(col, 1, 0, lo1, hi1);        // [1,0] = empty zero-interval
    modal_interval(col, lo1, hi1, lo2, hi2);    // second pass on x_blur * ~mask

    // y[d] = x[d] on [lo1,hi1];  z[d] = x[d] on [lo2,hi2] \ [lo1,hi1]
    float sy = 0.0f, syd = 0.0f, sz = 0.0f, szd = 0.0f;
    #pragma unroll 4
    for (int d = 0; d < DIMD; ++d) {
        float v  = col[d * BLK];
        float fd = (float)d;
        bool in1 = (d >= lo1) && (d <= hi1);
        bool in2 = (d >= lo2) && (d <= hi2);
        if (in1)      { sy += v; syd = fmaf(v, fd, syd); }
        else if (in2) { sz += v; szd = fmaf(v, fd, szd); }
    }

    const bool pick_y = (sy >= sz);
    const float num = pick_y ? syd : szd;
    const float den = pick_y ? sy  : sz;        // den > 0 guaranteed (interval holds argmax, x>0)
    out[pix0 + tid] = __fdiv_rn(num, den);
}

extern "C" void kernel_launch(void* const* d_in, const int* in_sizes, int n_in,
                              void* d_out, int out_size)
{
    const float* x   = (const float*)d_in[0];
    float*       out = (float*)d_out;

    // 96KB dynamic smem per block (static limit is 48KB). Host-side attribute
    // set is not a stream op — safe under graph capture; idempotent per call.
    cudaFuncSetAttribute(dme_kernel,
                         cudaFuncAttributeMaxDynamicSharedMemorySize, SMEM_BYTES);

    dme_kernel<<<NPIX / BLK, BLK, SMEM_BYTES>>>(x, out);
}